// round 1
// baseline (speedup 1.0000x reference)
#include <cuda_runtime.h>

#define NMAX 100000
#define EMAX 1600000
#define D 16

// ---------------- scratch (static __device__, no allocation) ----------------
__device__ float g_h_node[NMAX * D];        // (node_sca@W_node^T+b)        [N,D]
__device__ float g_h_node_sca[NMAX * D];    // (node_sca@W_node_sca^T+b)    [N,D]
__device__ float g_hv[NMAX * D * 3];        // vn(node_vec, W_node_vec)     [N,D,3]
__device__ float g_avh[NMAX * D * 3];       // vn(node_vec, W_vec_attn)+b   [N,D,3]
__device__ int   g_deg[NMAX];
__device__ int   g_off[NMAX + 1];
__device__ int   g_fill[NMAX];
__device__ int   g_eid[EMAX];

// ---------------- init ----------------
__global__ void k_zero(int n) {
    int i = blockIdx.x * blockDim.x + threadIdx.x;
    if (i < n) { g_deg[i] = 0; g_fill[i] = 0; }
}

// ---------------- per-node feature precompute ----------------
__global__ void k_node(const float* __restrict__ node_sca,
                       const float* __restrict__ node_vec,
                       const float* __restrict__ W_node,  const float* __restrict__ b_node,
                       const float* __restrict__ W_node_sca, const float* __restrict__ b_node_sca,
                       const float* __restrict__ W_node_vec,
                       const float* __restrict__ W_vec_attn, const float* __restrict__ b_vec_attn,
                       int n)
{
    int t = blockIdx.x * blockDim.x + threadIdx.x;
    if (t >= n * D) return;
    int nid = t >> 4, d = t & 15;
    const float* ns = node_sca + nid * 13;
    float h = b_node[d], hs = b_node_sca[d];
#pragma unroll
    for (int c = 0; c < 13; c++) {
        float x = ns[c];
        h  += W_node[d * 13 + c] * x;
        hs += W_node_sca[d * 13 + c] * x;
    }
    g_h_node[t] = h;
    g_h_node_sca[t] = hs;
    float w0 = W_node_vec[d * 2], w1 = W_node_vec[d * 2 + 1];
    float a0 = W_vec_attn[d * 2], a1 = W_vec_attn[d * 2 + 1], bv = b_vec_attn[d];
#pragma unroll
    for (int k = 0; k < 3; k++) {
        float n0 = node_vec[nid * 6 + k];
        float n1 = node_vec[nid * 6 + 3 + k];
        g_hv[t * 3 + k]  = w0 * n0 + w1 * n1;
        g_avh[t * 3 + k] = a0 * n0 + a1 * n1 + bv;
    }
}

// ---------------- CSR build ----------------
__global__ void k_hist(const int* __restrict__ edge_index, int ne) {
    int e = blockIdx.x * blockDim.x + threadIdx.x;
    if (e < ne) atomicAdd(&g_deg[edge_index[e]], 1);
}

__global__ void k_scan(int n) {
    __shared__ int sw[32];
    __shared__ int s_carry;
    int tid = threadIdx.x, lane = tid & 31, w = tid >> 5;
    if (tid == 0) { s_carry = 0; g_off[0] = 0; }
    __syncthreads();
    for (int base = 0; base < n; base += 1024) {
        int i = base + tid;
        int v = (i < n) ? g_deg[i] : 0;
        int x = v;
#pragma unroll
        for (int o = 1; o < 32; o <<= 1) {
            int y = __shfl_up_sync(0xffffffffu, x, o);
            if (lane >= o) x += y;
        }
        if (lane == 31) sw[w] = x;
        __syncthreads();
        if (w == 0) {
            int y = sw[lane];
#pragma unroll
            for (int o = 1; o < 32; o <<= 1) {
                int z = __shfl_up_sync(0xffffffffu, y, o);
                if (lane >= o) y += z;
            }
            sw[lane] = y;
        }
        __syncthreads();
        int pre = (w > 0) ? sw[w - 1] : 0;
        int incl = x + pre + s_carry;
        if (i < n) g_off[i + 1] = incl;
        __syncthreads();
        if (tid == 1023) s_carry = incl;
        __syncthreads();
    }
}

__global__ void k_scatter(const int* __restrict__ edge_index, int ne) {
    int e = blockIdx.x * blockDim.x + threadIdx.x;
    if (e < ne) {
        int s = edge_index[e];
        int p = g_off[s] + atomicAdd(&g_fill[s], 1);
        g_eid[p] = e;
    }
}

// ---------------- main: warp per node, online softmax + fused output ----------------
__global__ void __launch_bounds__(256) k_main(
    const float* __restrict__ node_sca, const float* __restrict__ node_pos,
    const float* __restrict__ edge_sca, const float* __restrict__ edge_vec,
    const int*   __restrict__ edge_index,
    const float* __restrict__ W_sca_attn, const float* __restrict__ b_sca_attn,
    const float* __restrict__ W_edge,     const float* __restrict__ b_edge,
    const float* __restrict__ W_edge_sca, const float* __restrict__ b_edge_sca,
    const float* __restrict__ W_edge_vec,
    const float* __restrict__ W_gv_vec1, const float* __restrict__ W_gv_vec2,
    const float* __restrict__ W_gv_sca,  const float* __restrict__ W_gate,
    const float* __restrict__ b_gate,    const float* __restrict__ W_dir,
    float* __restrict__ out, int n, int ne)
{
    // output-stage weights in smem, transposed so lanes hit distinct banks
    __shared__ float sW1[256], sW2[256], sWg[256], sWd[256], sWgs[512], sbg[16];
    for (int i = threadIdx.x; i < 256; i += blockDim.x) {
        int o = i >> 4, j = i & 15;
        sW1[j * 16 + o] = W_gv_vec1[i];
        sW2[j * 16 + o] = W_gv_vec2[i];
        sWg[j * 16 + o] = W_gate[i];
        sWd[j * 16 + o] = W_dir[i];
    }
    for (int i = threadIdx.x; i < 512; i += blockDim.x) {
        int o = i >> 5, j = i & 31;
        sWgs[j * 16 + o] = W_gv_sca[i];
    }
    if (threadIdx.x < 16) sbg[threadIdx.x] = b_gate[threadIdx.x];
    __syncthreads();

    int gw = (blockIdx.x * blockDim.x + threadIdx.x) >> 5;
    if (gw >= n) return;
    int lane = threadIdx.x & 31, d = lane & 15, half = lane >> 4;
    int nid = gw;

    // per-lane weight rows (registers)
    float Wa[14];
#pragma unroll
    for (int c = 0; c < 14; c++) Wa[c] = W_sca_attn[d * 27 + 13 + c];
    float lbase = b_sca_attn[d];
    {
        const float* ns = node_sca + nid * 13;
#pragma unroll
        for (int c = 0; c < 13; c++) lbase += W_sca_attn[d * 27 + c] * ns[c];
    }
    float We0 = W_edge[d * 4], We1 = W_edge[d * 4 + 1], We2 = W_edge[d * 4 + 2], We3 = W_edge[d * 4 + 3];
    float Ws0 = W_edge_sca[d * 4], Ws1 = W_edge_sca[d * 4 + 1], Ws2 = W_edge_sca[d * 4 + 2], Ws3 = W_edge_sca[d * 4 + 3];
    float be = b_edge[d], bes = b_edge_sca[d];
    float wev = W_edge_vec[d];
    float hn = g_h_node[nid * 16 + d];
    float hnswev = g_h_node_sca[nid * 16 + d] * wev;
    float hv0 = g_hv[(nid * 16 + d) * 3 + 0];
    float hv1 = g_hv[(nid * 16 + d) * 3 + 1];
    float hv2 = g_hv[(nid * 16 + d) * 3 + 2];
    float av0 = g_avh[(nid * 16 + d) * 3 + 0];
    float av1 = g_avh[(nid * 16 + d) * 3 + 1];
    float av2 = g_avh[(nid * 16 + d) * 3 + 2];
    float px = node_pos[nid * 3], py = node_pos[nid * 3 + 1], pz = node_pos[nid * 3 + 2];

    int beg = g_off[nid];
    int cnt = g_off[nid + 1] - beg;

    float m = -1e30f, s = 0.f, acc = 0.f;
    float vxA = 0.f, vyA = 0.f, vzA = 0.f;

    for (int ii = 0; ii < cnt; ii += 2) {
        int my = ii + half;
        bool act = my < cnt;
        int e = g_eid[beg + (act ? my : 0)];
        int dst = edge_index[ne + e];
        float qx = node_pos[dst * 3], qy = node_pos[dst * 3 + 1], qz = node_pos[dst * 3 + 2];
        float dx = px - qx, dy = py - qy, dz = pz - qz;
        float dist = sqrtf(dx * dx + dy * dy + dz * dz);
        const float* nd = node_sca + dst * 13;
        float lg = lbase + Wa[13] * dist;
#pragma unroll
        for (int c = 0; c < 13; c++) lg += Wa[c] * nd[c];
        // vector attention: per-d partial dot, reduce over 16 lanes of this half
        const float* ad = g_avh + (dst * 16 + d) * 3;
        float pd = av0 * ad[0] + av1 * ad[1] + av2 * ad[2];
        pd += __shfl_xor_sync(0xffffffffu, pd, 1);
        pd += __shfl_xor_sync(0xffffffffu, pd, 2);
        pd += __shfl_xor_sync(0xffffffffu, pd, 4);
        pd += __shfl_xor_sync(0xffffffffu, pd, 8);
        float avw = 1.f / (1.f + __expf(-pd));
        const float* es = edge_sca + e * 4;
        float e0 = es[0], e1 = es[1], e2 = es[2], e3 = es[3];
        float eh1 = be + We0 * e0 + We1 * e1 + We2 * e2 + We3 * e3;
        float eh2 = bes + Ws0 * e0 + Ws1 * e1 + Ws2 * e2 + Ws3 * e3;
        float msca = hn * eh1;
        float mn = fmaxf(m, lg);
        float scale = __expf(m - mn);
        float p = __expf(lg - mn);
        float c1 = hnswev * avw, c2 = eh2 * avw;
        const float* ev = edge_vec + e * 3;
        float evx = ev[0], evy = ev[1], evz = ev[2];
        if (act) {
            m = mn;
            s = s * scale + p;
            acc = acc * scale + p * msca;
            vxA += c1 * evx + c2 * hv0;
            vyA += c1 * evy + c2 * hv1;
            vzA += c1 * evz + c2 * hv2;
        }
    }

    // merge the two half-warp softmax states
    {
        float m2 = __shfl_xor_sync(0xffffffffu, m, 16);
        float s2 = __shfl_xor_sync(0xffffffffu, s, 16);
        float a2 = __shfl_xor_sync(0xffffffffu, acc, 16);
        float mm = fmaxf(m, m2);
        float f1 = __expf(m - mm), f2 = __expf(m2 - mm);
        s = s * f1 + s2 * f2;
        acc = acc * f1 + a2 * f2;
        vxA += __shfl_xor_sync(0xffffffffu, vxA, 16);
        vyA += __shfl_xor_sync(0xffffffffu, vyA, 16);
        vzA += __shfl_xor_sync(0xffffffffu, vzA, 16);
    }
    float emb = (s > 0.f) ? acc / s : 0.f;   // emb_sca[d]
    // emb_vec[d] = (vxA, vyA, vzA)

    // ---- fused GVPerceptron output stage (cross-lane via shfl, width 16) ----
    float v1x = 0.f, v1y = 0.f, v1z = 0.f;
#pragma unroll
    for (int j = 0; j < 16; j++) {
        float w = sW1[j * 16 + d];
        v1x += w * __shfl_sync(0xffffffffu, vxA, j, 16);
        v1y += w * __shfl_sync(0xffffffffu, vyA, j, 16);
        v1z += w * __shfl_sync(0xffffffffu, vzA, j, 16);
    }
    float vn = sqrtf(v1x * v1x + v1y * v1y + v1z * v1z + 1e-12f);
    float osca = 0.f;
#pragma unroll
    for (int j = 0; j < 16; j++) {
        osca += sWgs[j * 16 + d] * __shfl_sync(0xffffffffu, vn, j, 16);
        osca += sWgs[(16 + j) * 16 + d] * __shfl_sync(0xffffffffu, emb, j, 16);
    }
    float gt = sbg[d];
#pragma unroll
    for (int j = 0; j < 16; j++)
        gt += sWg[j * 16 + d] * __shfl_sync(0xffffffffu, osca, j, 16);
    gt = 1.f / (1.f + __expf(-gt));
    float ox = 0.f, oy = 0.f, oz = 0.f;
#pragma unroll
    for (int j = 0; j < 16; j++) {
        float w = sW2[j * 16 + d];
        ox += w * __shfl_sync(0xffffffffu, v1x, j, 16);
        oy += w * __shfl_sync(0xffffffffu, v1y, j, 16);
        oz += w * __shfl_sync(0xffffffffu, v1z, j, 16);
    }
    ox *= gt; oy *= gt; oz *= gt;
    float osca_o = (osca >= 0.f) ? osca : 0.2f * osca;
    float dxv = 0.f, dyv = 0.f, dzv = 0.f;
#pragma unroll
    for (int j = 0; j < 16; j++) {
        float w = sWd[j * 16 + d];
        dxv += w * __shfl_sync(0xffffffffu, ox, j, 16);
        dyv += w * __shfl_sync(0xffffffffu, oy, j, 16);
        dzv += w * __shfl_sync(0xffffffffu, oz, j, 16);
    }
    float dot = ox * dxv + oy * dyv + oz * dzv;
    float dd = dxv * dxv + dyv * dyv + dzv * dzv + 1e-6f;
    float t = dot / dd;
    float prx = ox - t * dxv, pry = oy - t * dyv, prz = oz - t * dzv;
    float fx = 0.2f * ox + 0.8f * ((dot >= 0.f) ? ox : prx);
    float fy = 0.2f * oy + 0.8f * ((dot >= 0.f) ? oy : pry);
    float fz = 0.2f * oz + 0.8f * ((dot >= 0.f) ? oz : prz);

    if (half == 0) {
        out[nid * 16 + d] = osca_o;
        size_t base = (size_t)n * 16 + (size_t)(nid * 16 + d) * 3;
        out[base + 0] = fx;
        out[base + 1] = fy;
        out[base + 2] = fz;
    }
}

// ---------------- launch ----------------
extern "C" void kernel_launch(void* const* d_in, const int* in_sizes, int n_in,
                              void* d_out, int out_size)
{
    const float* node_sca   = (const float*)d_in[0];
    const float* node_vec   = (const float*)d_in[1];
    const float* node_pos   = (const float*)d_in[2];
    const float* edge_sca   = (const float*)d_in[3];
    const float* edge_vec   = (const float*)d_in[4];
    const int*   edge_index = (const int*)  d_in[5];
    const float* W_sca_attn = (const float*)d_in[6];
    const float* b_sca_attn = (const float*)d_in[7];
    const float* W_vec_attn = (const float*)d_in[8];
    const float* b_vec_attn = (const float*)d_in[9];
    const float* W_node     = (const float*)d_in[10];
    const float* b_node     = (const float*)d_in[11];
    const float* W_edge     = (const float*)d_in[12];
    const float* b_edge     = (const float*)d_in[13];
    const float* W_node_sca = (const float*)d_in[14];
    const float* b_node_sca = (const float*)d_in[15];
    const float* W_node_vec = (const float*)d_in[16];
    const float* W_edge_sca = (const float*)d_in[17];
    const float* b_edge_sca = (const float*)d_in[18];
    const float* W_edge_vec = (const float*)d_in[19];
    const float* W_gv_vec1  = (const float*)d_in[20];
    const float* W_gv_vec2  = (const float*)d_in[21];
    const float* W_gv_sca   = (const float*)d_in[22];
    const float* W_gate     = (const float*)d_in[23];
    const float* b_gate     = (const float*)d_in[24];
    const float* W_dir      = (const float*)d_in[25];

    int n  = in_sizes[2] / 3;   // node_pos
    int ne = in_sizes[5] / 2;   // edge_index

    k_zero<<<(n + 255) / 256, 256>>>(n);
    k_node<<<(n * D + 127) / 128, 128>>>(node_sca, node_vec,
                                         W_node, b_node, W_node_sca, b_node_sca,
                                         W_node_vec, W_vec_attn, b_vec_attn, n);
    k_hist<<<(ne + 255) / 256, 256>>>(edge_index, ne);
    k_scan<<<1, 1024>>>(n);
    k_scatter<<<(ne + 255) / 256, 256>>>(edge_index, ne);
    k_main<<<(n + 7) / 8, 256>>>(node_sca, node_pos, edge_sca, edge_vec, edge_index,
                                 W_sca_attn, b_sca_attn, W_edge, b_edge,
                                 W_edge_sca, b_edge_sca, W_edge_vec,
                                 W_gv_vec1, W_gv_vec2, W_gv_sca, W_gate, b_gate, W_dir,
                                 (float*)d_out, n, ne);
}

// round 2
// speedup vs baseline: 1.4758x; 1.4758x over previous
#include <cuda_runtime.h>

#define NMAX 100000
#define EMAX 1600000
#define D 16

// ---------------- scratch (static __device__, no allocation) ----------------
__device__ float g_h_node[NMAX * D];        // (node_sca@W_node^T+b)        [N,D]
__device__ float g_h_node_sca[NMAX * D];    // (node_sca@W_node_sca^T+b)    [N,D]
__device__ float g_hv[NMAX * D * 3];        // vn(node_vec, W_node_vec)     [N,D,3]
__device__ float g_avh[NMAX * D * 3];       // vn(node_vec, W_vec_attn)+b   [N,D,3]
__device__ float g_lgdst[NMAX * D];         // dst-side logit contribution  [N,D]
__device__ float g_dist[EMAX];              // per-edge distance
__device__ int   g_deg[NMAX];
__device__ int   g_off[NMAX];
__device__ int   g_fill[NMAX];
__device__ int   g_eid[EMAX];
__device__ int   g_total;

// ---------------- init ----------------
__global__ void k_zero(int n) {
    int i = blockIdx.x * blockDim.x + threadIdx.x;
    if (i < n) { g_deg[i] = 0; g_fill[i] = 0; }
    if (i == 0) g_total = 0;
}

// ---------------- per-node feature precompute ----------------
__global__ void k_node(const float* __restrict__ node_sca,
                       const float* __restrict__ node_vec,
                       const float* __restrict__ W_node,  const float* __restrict__ b_node,
                       const float* __restrict__ W_node_sca, const float* __restrict__ b_node_sca,
                       const float* __restrict__ W_node_vec,
                       const float* __restrict__ W_vec_attn, const float* __restrict__ b_vec_attn,
                       const float* __restrict__ W_sca_attn,
                       int n)
{
    int t = blockIdx.x * blockDim.x + threadIdx.x;
    if (t >= n * D) return;
    int nid = t >> 4, d = t & 15;
    const float* ns = node_sca + nid * 13;
    float h = b_node[d], hs = b_node_sca[d], lgd = 0.f;
#pragma unroll
    for (int c = 0; c < 13; c++) {
        float x = ns[c];
        h   += W_node[d * 13 + c] * x;
        hs  += W_node_sca[d * 13 + c] * x;
        lgd += W_sca_attn[d * 27 + 13 + c] * x;   // dst block of attention weights
    }
    g_h_node[t] = h;
    g_h_node_sca[t] = hs;
    g_lgdst[t] = lgd;
    float w0 = W_node_vec[d * 2], w1 = W_node_vec[d * 2 + 1];
    float a0 = W_vec_attn[d * 2], a1 = W_vec_attn[d * 2 + 1], bv = b_vec_attn[d];
#pragma unroll
    for (int k = 0; k < 3; k++) {
        float n0 = node_vec[nid * 6 + k];
        float n1 = node_vec[nid * 6 + 3 + k];
        g_hv[t * 3 + k]  = w0 * n0 + w1 * n1;
        g_avh[t * 3 + k] = a0 * n0 + a1 * n1 + bv;
    }
}

// ---------------- edge pass: histogram + distance ----------------
__global__ void k_edge(const int* __restrict__ edge_index,
                       const float* __restrict__ node_pos, int ne) {
    int e = blockIdx.x * blockDim.x + threadIdx.x;
    if (e >= ne) return;
    int s = edge_index[e];
    int t = edge_index[ne + e];
    atomicAdd(&g_deg[s], 1);
    float dx = node_pos[s * 3]     - node_pos[t * 3];
    float dy = node_pos[s * 3 + 1] - node_pos[t * 3 + 1];
    float dz = node_pos[s * 3 + 2] - node_pos[t * 3 + 2];
    g_dist[e] = sqrtf(dx * dx + dy * dy + dz * dz);
}

// ---------------- warp-aggregated segment allocation (offsets need not be sorted) ----
__global__ void k_alloc(int n) {
    int i = blockIdx.x * blockDim.x + threadIdx.x;
    int lane = threadIdx.x & 31;
    int dg = (i < n) ? g_deg[i] : 0;
    int x = dg;
#pragma unroll
    for (int o = 1; o < 32; o <<= 1) {
        int y = __shfl_up_sync(0xffffffffu, x, o);
        if (lane >= o) x += y;
    }
    int total = __shfl_sync(0xffffffffu, x, 31);
    int base = 0;
    if (lane == 0) base = atomicAdd(&g_total, total);
    base = __shfl_sync(0xffffffffu, base, 0);
    if (i < n) g_off[i] = base + x - dg;
}

__global__ void k_scatter(const int* __restrict__ edge_index, int ne) {
    int e = blockIdx.x * blockDim.x + threadIdx.x;
    if (e < ne) {
        int s = edge_index[e];
        int p = g_off[s] + atomicAdd(&g_fill[s], 1);
        g_eid[p] = e;
    }
}

// ---------------- main: warp per node, online softmax + fused output ----------------
__global__ void __launch_bounds__(256) k_main(
    const float* __restrict__ node_sca,
    const float* __restrict__ edge_sca, const float* __restrict__ edge_vec,
    const int*   __restrict__ edge_index,
    const float* __restrict__ W_sca_attn, const float* __restrict__ b_sca_attn,
    const float* __restrict__ W_edge,     const float* __restrict__ b_edge,
    const float* __restrict__ W_edge_sca, const float* __restrict__ b_edge_sca,
    const float* __restrict__ W_edge_vec,
    const float* __restrict__ W_gv_vec1, const float* __restrict__ W_gv_vec2,
    const float* __restrict__ W_gv_sca,  const float* __restrict__ W_gate,
    const float* __restrict__ b_gate,    const float* __restrict__ W_dir,
    float* __restrict__ out, int n, int ne)
{
    __shared__ float sW1[256], sW2[256], sWg[256], sWd[256], sWgs[512], sbg[16];
    for (int i = threadIdx.x; i < 256; i += blockDim.x) {
        int o = i >> 4, j = i & 15;
        sW1[j * 16 + o] = W_gv_vec1[i];
        sW2[j * 16 + o] = W_gv_vec2[i];
        sWg[j * 16 + o] = W_gate[i];
        sWd[j * 16 + o] = W_dir[i];
    }
    for (int i = threadIdx.x; i < 512; i += blockDim.x) {
        int o = i >> 5, j = i & 31;
        sWgs[j * 16 + o] = W_gv_sca[i];
    }
    if (threadIdx.x < 16) sbg[threadIdx.x] = b_gate[threadIdx.x];
    __syncthreads();

    int gw = (blockIdx.x * blockDim.x + threadIdx.x) >> 5;
    if (gw >= n) return;
    int lane = threadIdx.x & 31, d = lane & 15, half = lane >> 4;
    int nid = gw;

    // src-side logit base + dist coefficient
    float lbase = b_sca_attn[d];
    {
        const float* ns = node_sca + nid * 13;
#pragma unroll
        for (int c = 0; c < 13; c++) lbase += W_sca_attn[d * 27 + c] * ns[c];
    }
    float wdist = W_sca_attn[d * 27 + 26];
    float We0 = W_edge[d * 4], We1 = W_edge[d * 4 + 1], We2 = W_edge[d * 4 + 2], We3 = W_edge[d * 4 + 3];
    float Ws0 = W_edge_sca[d * 4], Ws1 = W_edge_sca[d * 4 + 1], Ws2 = W_edge_sca[d * 4 + 2], Ws3 = W_edge_sca[d * 4 + 3];
    float be = b_edge[d], bes = b_edge_sca[d];
    float wev = W_edge_vec[d];
    float hn = g_h_node[nid * 16 + d];
    float hnswev = g_h_node_sca[nid * 16 + d] * wev;
    float hv0 = g_hv[(nid * 16 + d) * 3 + 0];
    float hv1 = g_hv[(nid * 16 + d) * 3 + 1];
    float hv2 = g_hv[(nid * 16 + d) * 3 + 2];
    float av0 = g_avh[(nid * 16 + d) * 3 + 0];
    float av1 = g_avh[(nid * 16 + d) * 3 + 1];
    float av2 = g_avh[(nid * 16 + d) * 3 + 2];

    int beg = g_off[nid];
    int cnt = g_deg[nid];

    float m = -1e30f, s = 0.f, acc = 0.f;
    float vxA = 0.f, vyA = 0.f, vzA = 0.f;

    for (int ii = 0; ii < cnt; ii += 2) {
        int my = ii + half;
        bool act = my < cnt;
        int e = g_eid[beg + (act ? my : 0)];
        int dst = edge_index[ne + e];
        float dist = g_dist[e];
        float lg = lbase + wdist * dist + g_lgdst[dst * 16 + d];
        const float* ad = g_avh + (dst * 16 + d) * 3;
        float pd = av0 * ad[0] + av1 * ad[1] + av2 * ad[2];
        pd += __shfl_xor_sync(0xffffffffu, pd, 1);
        pd += __shfl_xor_sync(0xffffffffu, pd, 2);
        pd += __shfl_xor_sync(0xffffffffu, pd, 4);
        pd += __shfl_xor_sync(0xffffffffu, pd, 8);
        float avw = 1.f / (1.f + __expf(-pd));
        float4 es = *(const float4*)(edge_sca + e * 4);
        float eh1 = be  + We0 * es.x + We1 * es.y + We2 * es.z + We3 * es.w;
        float eh2 = bes + Ws0 * es.x + Ws1 * es.y + Ws2 * es.z + Ws3 * es.w;
        float msca = hn * eh1;
        float mn = fmaxf(m, lg);
        float scale = __expf(m - mn);
        float p = __expf(lg - mn);
        float c1 = hnswev * avw, c2 = eh2 * avw;
        const float* ev = edge_vec + e * 3;
        float evx = ev[0], evy = ev[1], evz = ev[2];
        if (act) {
            m = mn;
            s = s * scale + p;
            acc = acc * scale + p * msca;
            vxA += c1 * evx + c2 * hv0;
            vyA += c1 * evy + c2 * hv1;
            vzA += c1 * evz + c2 * hv2;
        }
    }

    // merge the two half-warp softmax states
    {
        float m2 = __shfl_xor_sync(0xffffffffu, m, 16);
        float s2 = __shfl_xor_sync(0xffffffffu, s, 16);
        float a2 = __shfl_xor_sync(0xffffffffu, acc, 16);
        float mm = fmaxf(m, m2);
        float f1 = __expf(m - mm), f2 = __expf(m2 - mm);
        s = s * f1 + s2 * f2;
        acc = acc * f1 + a2 * f2;
        vxA += __shfl_xor_sync(0xffffffffu, vxA, 16);
        vyA += __shfl_xor_sync(0xffffffffu, vyA, 16);
        vzA += __shfl_xor_sync(0xffffffffu, vzA, 16);
    }
    float emb = (s > 0.f) ? acc / s : 0.f;

    // ---- fused GVPerceptron output stage (cross-lane via shfl, width 16) ----
    float v1x = 0.f, v1y = 0.f, v1z = 0.f;
#pragma unroll
    for (int j = 0; j < 16; j++) {
        float w = sW1[j * 16 + d];
        v1x += w * __shfl_sync(0xffffffffu, vxA, j, 16);
        v1y += w * __shfl_sync(0xffffffffu, vyA, j, 16);
        v1z += w * __shfl_sync(0xffffffffu, vzA, j, 16);
    }
    float vn = sqrtf(v1x * v1x + v1y * v1y + v1z * v1z + 1e-12f);
    float osca = 0.f;
#pragma unroll
    for (int j = 0; j < 16; j++) {
        osca += sWgs[j * 16 + d] * __shfl_sync(0xffffffffu, vn, j, 16);
        osca += sWgs[(16 + j) * 16 + d] * __shfl_sync(0xffffffffu, emb, j, 16);
    }
    float gt = sbg[d];
#pragma unroll
    for (int j = 0; j < 16; j++)
        gt += sWg[j * 16 + d] * __shfl_sync(0xffffffffu, osca, j, 16);
    gt = 1.f / (1.f + __expf(-gt));
    float ox = 0.f, oy = 0.f, oz = 0.f;
#pragma unroll
    for (int j = 0; j < 16; j++) {
        float w = sW2[j * 16 + d];
        ox += w * __shfl_sync(0xffffffffu, v1x, j, 16);
        oy += w * __shfl_sync(0xffffffffu, v1y, j, 16);
        oz += w * __shfl_sync(0xffffffffu, v1z, j, 16);
    }
    ox *= gt; oy *= gt; oz *= gt;
    float osca_o = (osca >= 0.f) ? osca : 0.2f * osca;
    float dxv = 0.f, dyv = 0.f, dzv = 0.f;
#pragma unroll
    for (int j = 0; j < 16; j++) {
        float w = sWd[j * 16 + d];
        dxv += w * __shfl_sync(0xffffffffu, ox, j, 16);
        dyv += w * __shfl_sync(0xffffffffu, oy, j, 16);
        dzv += w * __shfl_sync(0xffffffffu, oz, j, 16);
    }
    float dot = ox * dxv + oy * dyv + oz * dzv;
    float dd = dxv * dxv + dyv * dyv + dzv * dzv + 1e-6f;
    float t = dot / dd;
    float prx = ox - t * dxv, pry = oy - t * dyv, prz = oz - t * dzv;
    float fx = 0.2f * ox + 0.8f * ((dot >= 0.f) ? ox : prx);
    float fy = 0.2f * oy + 0.8f * ((dot >= 0.f) ? oy : pry);
    float fz = 0.2f * oz + 0.8f * ((dot >= 0.f) ? oz : prz);

    if (half == 0) {
        out[nid * 16 + d] = osca_o;
        size_t base = (size_t)n * 16 + (size_t)(nid * 16 + d) * 3;
        out[base + 0] = fx;
        out[base + 1] = fy;
        out[base + 2] = fz;
    }
}

// ---------------- launch ----------------
extern "C" void kernel_launch(void* const* d_in, const int* in_sizes, int n_in,
                              void* d_out, int out_size)
{
    const float* node_sca   = (const float*)d_in[0];
    const float* node_vec   = (const float*)d_in[1];
    const float* node_pos   = (const float*)d_in[2];
    const float* edge_sca   = (const float*)d_in[3];
    const float* edge_vec   = (const float*)d_in[4];
    const int*   edge_index = (const int*)  d_in[5];
    const float* W_sca_attn = (const float*)d_in[6];
    const float* b_sca_attn = (const float*)d_in[7];
    const float* W_vec_attn = (const float*)d_in[8];
    const float* b_vec_attn = (const float*)d_in[9];
    const float* W_node     = (const float*)d_in[10];
    const float* b_node     = (const float*)d_in[11];
    const float* W_edge     = (const float*)d_in[12];
    const float* b_edge     = (const float*)d_in[13];
    const float* W_node_sca = (const float*)d_in[14];
    const float* b_node_sca = (const float*)d_in[15];
    const float* W_node_vec = (const float*)d_in[16];
    const float* W_edge_sca = (const float*)d_in[17];
    const float* b_edge_sca = (const float*)d_in[18];
    const float* W_edge_vec = (const float*)d_in[19];
    const float* W_gv_vec1  = (const float*)d_in[20];
    const float* W_gv_vec2  = (const float*)d_in[21];
    const float* W_gv_sca   = (const float*)d_in[22];
    const float* W_gate     = (const float*)d_in[23];
    const float* b_gate     = (const float*)d_in[24];
    const float* W_dir      = (const float*)d_in[25];

    int n  = in_sizes[2] / 3;   // node_pos
    int ne = in_sizes[5] / 2;   // edge_index

    k_zero<<<(n + 255) / 256, 256>>>(n);
    k_node<<<(n * D + 127) / 128, 128>>>(node_sca, node_vec,
                                         W_node, b_node, W_node_sca, b_node_sca,
                                         W_node_vec, W_vec_attn, b_vec_attn,
                                         W_sca_attn, n);
    k_edge<<<(ne + 255) / 256, 256>>>(edge_index, node_pos, ne);
    k_alloc<<<(n + 255) / 256, 256>>>(n);
    k_scatter<<<(ne + 255) / 256, 256>>>(edge_index, ne);
    k_main<<<(n + 7) / 8, 256>>>(node_sca, edge_sca, edge_vec, edge_index,
                                 W_sca_attn, b_sca_attn, W_edge, b_edge,
                                 W_edge_sca, b_edge_sca, W_edge_vec,
                                 W_gv_vec1, W_gv_vec2, W_gv_sca, W_gate, b_gate, W_dir,
                                 (float*)d_out, n, ne);
}

// round 4
// speedup vs baseline: 1.7092x; 1.1582x over previous
#include <cuda_runtime.h>

#define NMAX 100000
#define EMAX 1600000
#define D 16

// ---------------- scratch (static __device__, no allocation) ----------------
__device__ float  g_h_node[NMAX * D];        // (node_sca@W_node^T+b)        [N,D]
__device__ float  g_h_node_sca[NMAX * D];    // (node_sca@W_node_sca^T+b)    [N,D]
__device__ float  g_hv[NMAX * D * 3];        // vn(node_vec, W_node_vec)     [N,D,3]
__device__ float  g_avh[NMAX * D * 3];       // vn(node_vec, W_vec_attn)+b   [N,D,3]
__device__ float  g_lgdst[NMAX * D];         // dst-side logit contribution  [N,D]
__device__ float4 g_recA[EMAX];              // (dist, ev.x, ev.y, ev.z) in CSR order
__device__ float4 g_recB[EMAX];              // edge_sca in CSR order
__device__ int    g_rdst[EMAX];              // dst in CSR order
__device__ int    g_deg[NMAX];
__device__ int    g_off[NMAX];
__device__ int    g_fill[NMAX];
__device__ int    g_total;

// ---------------- init ----------------
__global__ void k_zero(int n) {
    int i = blockIdx.x * blockDim.x + threadIdx.x;
    if (i < n) { g_deg[i] = 0; g_fill[i] = 0; }
    if (i == 0) g_total = 0;
}

// ---------------- per-node feature precompute ----------------
__global__ void k_node(const float* __restrict__ node_sca,
                       const float* __restrict__ node_vec,
                       const float* __restrict__ W_node,  const float* __restrict__ b_node,
                       const float* __restrict__ W_node_sca, const float* __restrict__ b_node_sca,
                       const float* __restrict__ W_node_vec,
                       const float* __restrict__ W_vec_attn, const float* __restrict__ b_vec_attn,
                       const float* __restrict__ W_sca_attn,
                       int n)
{
    int t = blockIdx.x * blockDim.x + threadIdx.x;
    if (t >= n * D) return;
    int nid = t >> 4, d = t & 15;
    const float* ns = node_sca + nid * 13;
    float h = b_node[d], hs = b_node_sca[d], lgd = 0.f;
#pragma unroll
    for (int c = 0; c < 13; c++) {
        float x = ns[c];
        h   += W_node[d * 13 + c] * x;
        hs  += W_node_sca[d * 13 + c] * x;
        lgd += W_sca_attn[d * 27 + 13 + c] * x;   // dst block of attention weights
    }
    g_h_node[t] = h;
    g_h_node_sca[t] = hs;
    g_lgdst[t] = lgd;
    float w0 = W_node_vec[d * 2], w1 = W_node_vec[d * 2 + 1];
    float a0 = W_vec_attn[d * 2], a1 = W_vec_attn[d * 2 + 1], bv = b_vec_attn[d];
#pragma unroll
    for (int k = 0; k < 3; k++) {
        float n0 = node_vec[nid * 6 + k];
        float n1 = node_vec[nid * 6 + 3 + k];
        g_hv[t * 3 + k]  = w0 * n0 + w1 * n1;
        g_avh[t * 3 + k] = a0 * n0 + a1 * n1 + bv;
    }
}

// ---------------- histogram ----------------
__global__ void k_hist(const int* __restrict__ edge_index, int ne) {
    int e = blockIdx.x * blockDim.x + threadIdx.x;
    if (e < ne) atomicAdd(&g_deg[edge_index[e]], 1);
}

// ---------------- warp-aggregated segment allocation ----------------
__global__ void k_alloc(int n) {
    int i = blockIdx.x * blockDim.x + threadIdx.x;
    int lane = threadIdx.x & 31;
    int dg = (i < n) ? g_deg[i] : 0;
    int x = dg;
#pragma unroll
    for (int o = 1; o < 32; o <<= 1) {
        int y = __shfl_up_sync(0xffffffffu, x, o);
        if (lane >= o) x += y;
    }
    int total = __shfl_sync(0xffffffffu, x, 31);
    int base = 0;
    if (lane == 0) base = atomicAdd(&g_total, total);
    base = __shfl_sync(0xffffffffu, base, 0);
    if (i < n) g_off[i] = base + x - dg;
}

// ---------------- scatter: build CSR-ordered edge records ----------------
__global__ void k_scatter(const int* __restrict__ edge_index,
                          const float* __restrict__ node_pos,
                          const float* __restrict__ edge_sca,
                          const float* __restrict__ edge_vec, int ne) {
    int e = blockIdx.x * blockDim.x + threadIdx.x;
    if (e >= ne) return;
    int s = edge_index[e];
    int t = edge_index[ne + e];
    int p = g_off[s] + atomicAdd(&g_fill[s], 1);
    float dx = node_pos[s * 3]     - node_pos[t * 3];
    float dy = node_pos[s * 3 + 1] - node_pos[t * 3 + 1];
    float dz = node_pos[s * 3 + 2] - node_pos[t * 3 + 2];
    float dist = sqrtf(dx * dx + dy * dy + dz * dz);
    const float* ev = edge_vec + e * 3;
    g_recA[p] = make_float4(dist, ev[0], ev[1], ev[2]);
    g_recB[p] = *(const float4*)(edge_sca + e * 4);
    g_rdst[p] = t;
}

// ---------------- main: warp per node, online softmax + fused output ----------------
__global__ void __launch_bounds__(256) k_main(
    const float* __restrict__ node_sca,
    const float* __restrict__ W_sca_attn, const float* __restrict__ b_sca_attn,
    const float* __restrict__ W_edge,     const float* __restrict__ b_edge,
    const float* __restrict__ W_edge_sca, const float* __restrict__ b_edge_sca,
    const float* __restrict__ W_edge_vec,
    const float* __restrict__ W_gv_vec1, const float* __restrict__ W_gv_vec2,
    const float* __restrict__ W_gv_sca,  const float* __restrict__ W_gate,
    const float* __restrict__ b_gate,    const float* __restrict__ W_dir,
    float* __restrict__ out, int n)
{
    __shared__ float sW1[256], sW2[256], sWg[256], sWd[256], sWgs[512], sbg[16];
    for (int i = threadIdx.x; i < 256; i += blockDim.x) {
        int o = i >> 4, j = i & 15;
        sW1[j * 16 + o] = W_gv_vec1[i];
        sW2[j * 16 + o] = W_gv_vec2[i];
        sWg[j * 16 + o] = W_gate[i];
        sWd[j * 16 + o] = W_dir[i];
    }
    for (int i = threadIdx.x; i < 512; i += blockDim.x) {
        int o = i >> 5, j = i & 31;
        sWgs[j * 16 + o] = W_gv_sca[i];
    }
    if (threadIdx.x < 16) sbg[threadIdx.x] = b_gate[threadIdx.x];
    __syncthreads();

    int gw = (blockIdx.x * blockDim.x + threadIdx.x) >> 5;
    if (gw >= n) return;
    int lane = threadIdx.x & 31, d = lane & 15, half = lane >> 4;
    int nid = gw;

    // src-side logit base + dist coefficient
    float lbase = b_sca_attn[d];
    {
        const float* ns = node_sca + nid * 13;
#pragma unroll
        for (int c = 0; c < 13; c++) lbase += W_sca_attn[d * 27 + c] * ns[c];
    }
    float wdist = W_sca_attn[d * 27 + 26];
    float We0 = W_edge[d * 4], We1 = W_edge[d * 4 + 1], We2 = W_edge[d * 4 + 2], We3 = W_edge[d * 4 + 3];
    float Ws0 = W_edge_sca[d * 4], Ws1 = W_edge_sca[d * 4 + 1], Ws2 = W_edge_sca[d * 4 + 2], Ws3 = W_edge_sca[d * 4 + 3];
    float be = b_edge[d], bes = b_edge_sca[d];
    float wev = W_edge_vec[d];
    float hn = g_h_node[nid * 16 + d];
    float hnswev = g_h_node_sca[nid * 16 + d] * wev;
    float hv0 = g_hv[(nid * 16 + d) * 3 + 0];
    float hv1 = g_hv[(nid * 16 + d) * 3 + 1];
    float hv2 = g_hv[(nid * 16 + d) * 3 + 2];
    float av0 = g_avh[(nid * 16 + d) * 3 + 0];
    float av1 = g_avh[(nid * 16 + d) * 3 + 1];
    float av2 = g_avh[(nid * 16 + d) * 3 + 2];

    int beg = g_off[nid];
    int cnt = g_deg[nid];

    float m = -1e30f, s = 0.f, acc = 0.f;
    float vxA = 0.f, vyA = 0.f, vzA = 0.f;

    for (int ii = 0; ii < cnt; ii += 2) {
        int my = ii + half;
        bool act = my < cnt;
        int idx = beg + min(my, cnt - 1);
        int dst = g_rdst[idx];
        float4 ra = g_recA[idx];          // dist, ev
        float4 es = g_recB[idx];          // edge_sca
        float lg = lbase + wdist * ra.x + g_lgdst[dst * 16 + d];
        const float* ad = g_avh + (dst * 16 + d) * 3;
        float pd = av0 * ad[0] + av1 * ad[1] + av2 * ad[2];
        pd += __shfl_xor_sync(0xffffffffu, pd, 1);
        pd += __shfl_xor_sync(0xffffffffu, pd, 2);
        pd += __shfl_xor_sync(0xffffffffu, pd, 4);
        pd += __shfl_xor_sync(0xffffffffu, pd, 8);
        float avw = 1.f / (1.f + __expf(-pd));
        float eh1 = be  + We0 * es.x + We1 * es.y + We2 * es.z + We3 * es.w;
        float eh2 = bes + Ws0 * es.x + Ws1 * es.y + Ws2 * es.z + Ws3 * es.w;
        float msca = hn * eh1;
        float mn = fmaxf(m, lg);
        float scale = __expf(m - mn);
        float p = __expf(lg - mn);
        float c1 = hnswev * avw, c2 = eh2 * avw;
        if (act) {
            m = mn;
            s = s * scale + p;
            acc = acc * scale + p * msca;
            vxA += c1 * ra.y + c2 * hv0;
            vyA += c1 * ra.z + c2 * hv1;
            vzA += c1 * ra.w + c2 * hv2;
        }
    }

    // merge the two half-warp softmax states
    {
        float m2 = __shfl_xor_sync(0xffffffffu, m, 16);
        float s2 = __shfl_xor_sync(0xffffffffu, s, 16);
        float a2 = __shfl_xor_sync(0xffffffffu, acc, 16);
        float mm = fmaxf(m, m2);
        float f1 = __expf(m - mm), f2 = __expf(m2 - mm);
        s = s * f1 + s2 * f2;
        acc = acc * f1 + a2 * f2;
        vxA += __shfl_xor_sync(0xffffffffu, vxA, 16);
        vyA += __shfl_xor_sync(0xffffffffu, vyA, 16);
        vzA += __shfl_xor_sync(0xffffffffu, vzA, 16);
    }
    float emb = (s > 0.f) ? acc / s : 0.f;

    // ---- fused GVPerceptron output stage (cross-lane via shfl, width 16) ----
    float v1x = 0.f, v1y = 0.f, v1z = 0.f;
#pragma unroll
    for (int j = 0; j < 16; j++) {
        float w = sW1[j * 16 + d];
        v1x += w * __shfl_sync(0xffffffffu, vxA, j, 16);
        v1y += w * __shfl_sync(0xffffffffu, vyA, j, 16);
        v1z += w * __shfl_sync(0xffffffffu, vzA, j, 16);
    }
    float vn = sqrtf(v1x * v1x + v1y * v1y + v1z * v1z + 1e-12f);
    float osca = 0.f;
#pragma unroll
    for (int j = 0; j < 16; j++) {
        osca += sWgs[j * 16 + d] * __shfl_sync(0xffffffffu, vn, j, 16);
        osca += sWgs[(16 + j) * 16 + d] * __shfl_sync(0xffffffffu, emb, j, 16);
    }
    float gt = sbg[d];
#pragma unroll
    for (int j = 0; j < 16; j++)
        gt += sWg[j * 16 + d] * __shfl_sync(0xffffffffu, osca, j, 16);
    gt = 1.f / (1.f + __expf(-gt));
    float ox = 0.f, oy = 0.f, oz = 0.f;
#pragma unroll
    for (int j = 0; j < 16; j++) {
        float w = sW2[j * 16 + d];
        ox += w * __shfl_sync(0xffffffffu, v1x, j, 16);
        oy += w * __shfl_sync(0xffffffffu, v1y, j, 16);
        oz += w * __shfl_sync(0xffffffffu, v1z, j, 16);
    }
    ox *= gt; oy *= gt; oz *= gt;
    float osca_o = (osca >= 0.f) ? osca : 0.2f * osca;
    float dxv = 0.f, dyv = 0.f, dzv = 0.f;
#pragma unroll
    for (int j = 0; j < 16; j++) {
        float w = sWd[j * 16 + d];
        dxv += w * __shfl_sync(0xffffffffu, ox, j, 16);
        dyv += w * __shfl_sync(0xffffffffu, oy, j, 16);
        dzv += w * __shfl_sync(0xffffffffu, oz, j, 16);
    }
    float dot = ox * dxv + oy * dyv + oz * dzv;
    float dd = dxv * dxv + dyv * dyv + dzv * dzv + 1e-6f;
    float t = dot / dd;
    float prx = ox - t * dxv, pry = oy - t * dyv, prz = oz - t * dzv;
    float fx = 0.2f * ox + 0.8f * ((dot >= 0.f) ? ox : prx);
    float fy = 0.2f * oy + 0.8f * ((dot >= 0.f) ? oy : pry);
    float fz = 0.2f * oz + 0.8f * ((dot >= 0.f) ? oz : prz);

    if (half == 0) {
        out[nid * 16 + d] = osca_o;
        size_t base = (size_t)n * 16 + (size_t)(nid * 16 + d) * 3;
        out[base + 0] = fx;
        out[base + 1] = fy;
        out[base + 2] = fz;
    }
}

// ---------------- launch ----------------
extern "C" void kernel_launch(void* const* d_in, const int* in_sizes, int n_in,
                              void* d_out, int out_size)
{
    const float* node_sca   = (const float*)d_in[0];
    const float* node_vec   = (const float*)d_in[1];
    const float* node_pos   = (const float*)d_in[2];
    const float* edge_sca   = (const float*)d_in[3];
    const float* edge_vec   = (const float*)d_in[4];
    const int*   edge_index = (const int*)  d_in[5];
    const float* W_sca_attn = (const float*)d_in[6];
    const float* b_sca_attn = (const float*)d_in[7];
    const float* W_vec_attn = (const float*)d_in[8];
    const float* b_vec_attn = (const float*)d_in[9];
    const float* W_node     = (const float*)d_in[10];
    const float* b_node     = (const float*)d_in[11];
    const float* W_edge     = (const float*)d_in[12];
    const float* b_edge     = (const float*)d_in[13];
    const float* W_node_sca = (const float*)d_in[14];
    const float* b_node_sca = (const float*)d_in[15];
    const float* W_node_vec = (const float*)d_in[16];
    const float* W_edge_sca = (const float*)d_in[17];
    const float* b_edge_sca = (const float*)d_in[18];
    const float* W_edge_vec = (const float*)d_in[19];
    const float* W_gv_vec1  = (const float*)d_in[20];
    const float* W_gv_vec2  = (const float*)d_in[21];
    const float* W_gv_sca   = (const float*)d_in[22];
    const float* W_gate     = (const float*)d_in[23];
    const float* b_gate     = (const float*)d_in[24];
    const float* W_dir      = (const float*)d_in[25];

    int n  = in_sizes[2] / 3;   // node_pos
    int ne = in_sizes[5] / 2;   // edge_index

    k_zero<<<(n + 255) / 256, 256>>>(n);
    k_node<<<(n * D + 127) / 128, 128>>>(node_sca, node_vec,
                                         W_node, b_node, W_node_sca, b_node_sca,
                                         W_node_vec, W_vec_attn, b_vec_attn,
                                         W_sca_attn, n);
    k_hist<<<(ne + 255) / 256, 256>>>(edge_index, ne);
    k_alloc<<<(n + 255) / 256, 256>>>(n);
    k_scatter<<<(ne + 255) / 256, 256>>>(edge_index, node_pos, edge_sca, edge_vec, ne);
    k_main<<<(n + 7) / 8, 256>>>(node_sca,
                                 W_sca_attn, b_sca_attn, W_edge, b_edge,
                                 W_edge_sca, b_edge_sca, W_edge_vec,
                                 W_gv_vec1, W_gv_vec2, W_gv_sca, W_gate, b_gate, W_dir,
                                 (float*)d_out, n);
}